// round 15
// baseline (speedup 1.0000x reference)
#include <cuda_runtime.h>
#include <cuda_bf16.h>
#include <math.h>

#define BB 65536
#define KK 256
#define DD 128
#define NITER 50
#define SNBLK 148          // k_sink: one persistent block per SM
#define SROWS 384          // smem-resident rows per block (192KB slab)
#define WBATCH 6           // 2-row smem batches per warp (static trip!)
#define GSTART (SNBLK * SROWS)          // 56832: first global-resident row
#define GBATCH ((BB - GSTART) / 2)      // 4352 leftover 2-row batches
#define TS_OFF (SROWS * 512)            // 196608
#define WSH_OFF (TS_OFF + 32768)        // 229376 (Ts: 32 warps x 256 f32)
#define SMEM_SINK (WSH_OFF + 1024)      // 230400 B

typedef unsigned long long u64;

// ---- scratch (static device globals; no allocation) ----
__device__ __nv_bfloat16 g_Kh[(size_t)BB * KK];  // K' in bf16 (32MB)
__device__ float g_ynT[DD * KK];         // normalized prototypes, k-major [k][j]
__device__ float g_xinv[BB];             // 1 / ||x_i||
__device__ float g_a[BB];                // exp(u)   (written on last iteration)
__device__ float g_T[3][KK * 32];        // column sums, padded 128B apart
__device__ unsigned g_bar;               // grid barrier counter
__device__ double g_sum;

// ---- packed f32x2 helpers ----
__device__ __forceinline__ void fma2(u64& d, u64 a, u64 b) {
    asm("fma.rn.f32x2 %0, %1, %2, %0;" : "+l"(d) : "l"(a), "l"(b));
}
__device__ __forceinline__ u64 add2(u64 a, u64 b) {
    u64 r; asm("add.rn.f32x2 %0, %1, %2;" : "=l"(r) : "l"(a), "l"(b)); return r;
}
__device__ __forceinline__ u64 packff(float lo, float hi) {
    u64 r; asm("mov.b64 %0, {%1, %2};" : "=l"(r) : "f"(lo), "f"(hi)); return r;
}
__device__ __forceinline__ void unpackff(u64 v, float& lo, float& hi) {
    asm("mov.b64 {%0, %1}, %2;" : "=f"(lo), "=f"(hi) : "l"(v));
}
__device__ __forceinline__ u64 bf2_to_f32x2(unsigned v) {
    unsigned lo = v << 16;
    unsigned hi = v & 0xFFFF0000u;
    u64 r; asm("mov.b64 %0, {%1, %2};" : "=l"(r) : "r"(lo), "r"(hi)); return r;
}

// ---------------------------------------------------------------------------
__global__ void k_init(const float* __restrict__ proto) {
    int j = threadIdx.x;  // 0..255
    float ss = 0.f;
#pragma unroll 8
    for (int k = 0; k < DD; k++) { float v = proto[j * DD + k]; ss += v * v; }
    float inv = __fdividef(1.f, fmaxf(sqrtf(ss), 1e-12f));
    for (int k = 0; k < DD; k++) g_ynT[k * KK + j] = proto[j * DD + k] * inv;
    const float nuP = 1.f / (float)KK + 1e-8f;
    g_T[0][j * 32] = nuP;   // makes w == 1 on iteration 1 (v0 = 0)
    g_T[1][j * 32] = 0.f;   // accumulation target of iteration 1
    if (j == 0) { g_sum = 0.0; g_bar = 0u; }
}

// ---------------------------------------------------------------------------
__global__ void k_xnorm(const float* __restrict__ x) {
    int warp = threadIdx.x >> 5, lane = threadIdx.x & 31;
    int row = blockIdx.x * 8 + warp;
    float4 v = ((const float4*)(x + (size_t)row * DD))[lane];
    float ss = v.x * v.x + v.y * v.y + v.z * v.z + v.w * v.w;
#pragma unroll
    for (int o = 16; o; o >>= 1) ss += __shfl_xor_sync(0xffffffffu, ss, o);
    if (lane == 0) g_xinv[row] = __fdividef(1.f, fmaxf(sqrtf(ss), 1e-12f));
}

// ---------------------------------------------------------------------------
// cost GEMM (R10 — proven, untouched): FFMA2; K' = exp(-10*(1-xn.yn))+1e-8, bf16
// ---------------------------------------------------------------------------
__global__ void k_gemm(const float* __restrict__ x) {
    __shared__ float ys[32 * 256];
    __shared__ float xs[64 * 32];
    __shared__ float xrn[64];

    int t = threadIdx.x;
    int rowBase = blockIdx.x * 64;
    if (t < 64) xrn[t] = g_xinv[rowBase + t];

    int tx = t & 31, ty = t >> 5;
    u64 acc[8][4];
#pragma unroll
    for (int i = 0; i < 8; i++)
#pragma unroll
        for (int j = 0; j < 4; j++) acc[i][j] = 0ull;

    for (int kc = 0; kc < 4; kc++) {
        __syncthreads();
        {
            const float4* src = (const float4*)(g_ynT + kc * 32 * 256);
            float4* dst = (float4*)ys;
#pragma unroll
            for (int i = 0; i < 8; i++) dst[t + i * 256] = src[t + i * 256];
        }
        {
#pragma unroll
            for (int i = 0; i < 2; i++) {
                int idx = t + i * 256;
                int r = idx >> 3;
                int c4 = idx & 7;
                float4 v = *(const float4*)(x + (size_t)(rowBase + r) * DD + kc * 32 + c4 * 4);
                *(float4*)&xs[r * 32 + c4 * 4] = v;
            }
        }
        __syncthreads();
#pragma unroll 4
        for (int k = 0; k < 32; k++) {
            float4 b0 = *(const float4*)&ys[k * 256 + tx * 8];
            float4 b1 = *(const float4*)&ys[k * 256 + tx * 8 + 4];
            u64 p0 = packff(b0.x, b0.y), p1 = packff(b0.z, b0.w);
            u64 p2 = packff(b1.x, b1.y), p3 = packff(b1.z, b1.w);
#pragma unroll
            for (int i = 0; i < 8; i++) {
                float a = xs[(ty * 8 + i) * 32 + k];
                u64 a2 = packff(a, a);
                fma2(acc[i][0], a2, p0);
                fma2(acc[i][1], a2, p1);
                fma2(acc[i][2], a2, p2);
                fma2(acc[i][3], a2, p3);
            }
        }
    }

#pragma unroll
    for (int i = 0; i < 8; i++) {
        int row = rowBase + ty * 8 + i;
        float inv = xrn[ty * 8 + i];
        float kv[8];
#pragma unroll
        for (int j = 0; j < 4; j++) {
            float lo, hi; unpackff(acc[i][j], lo, hi);
            float c0 = 1.f - lo * inv;
            float c1 = 1.f - hi * inv;
            kv[2 * j]     = __expf(-10.f * c0) + 1e-8f;
            kv[2 * j + 1] = __expf(-10.f * c1) + 1e-8f;
        }
        __nv_bfloat162 h0 = __float22bfloat162_rn(make_float2(kv[0], kv[1]));
        __nv_bfloat162 h1 = __float22bfloat162_rn(make_float2(kv[2], kv[3]));
        __nv_bfloat162 h2 = __float22bfloat162_rn(make_float2(kv[4], kv[5]));
        __nv_bfloat162 h3 = __float22bfloat162_rn(make_float2(kv[6], kv[7]));
        uint4 s;
        s.x = *(unsigned*)&h0; s.y = *(unsigned*)&h1;
        s.z = *(unsigned*)&h2; s.w = *(unsigned*)&h3;
        *(uint4*)&g_Kh[(size_t)row * KK + tx * 8] = s;
    }
}

// ---------------------------------------------------------------------------
// one row-half (16 bf16 in q[4]): s over 16-lane half, a = mu/s, tj += K*a
// ---------------------------------------------------------------------------
__device__ __forceinline__ void comp_row(int row, const u64* q, const u64* w2,
                                         u64* tj2, float muP, bool storeA, int hl) {
    u64 pr[8];
#pragma unroll
    for (int i = 0; i < 4; i++) {
        unsigned lo32 = (unsigned)(q[i] & 0xffffffffull);
        unsigned hi32 = (unsigned)(q[i] >> 32);
        pr[2 * i]     = bf2_to_f32x2(lo32);
        pr[2 * i + 1] = bf2_to_f32x2(hi32);
    }
    u64 t0 = 0, t1 = 0, t2 = 0, t3 = 0;
    fma2(t0, pr[0], w2[0]); fma2(t1, pr[1], w2[1]);
    fma2(t2, pr[2], w2[2]); fma2(t3, pr[3], w2[3]);
    fma2(t0, pr[4], w2[4]); fma2(t1, pr[5], w2[5]);
    fma2(t2, pr[6], w2[6]); fma2(t3, pr[7], w2[7]);
    u64 tt = add2(add2(t0, t1), add2(t2, t3));
    float slo, shi; unpackff(tt, slo, shi);
    float s = slo + shi;
#pragma unroll
    for (int o = 8; o; o >>= 1) s += __shfl_xor_sync(0xffffffffu, s, o);
    float a = muP * __fdividef(1.f, s);
    if (storeA && hl == 0) g_a[row] = a;
    u64 a2 = packff(a, a);
#pragma unroll
    for (int k = 0; k < 8; k++) fma2(tj2[k], pr[k], a2);
}

__device__ __forceinline__ void ldq_g(int row, int hl, u64* q) {
    const __nv_bfloat16* p = g_Kh + (size_t)row * KK + hl * 16;
    asm volatile("ld.global.L2::evict_last.v4.b64 {%0,%1,%2,%3}, [%4];"
                 : "=l"(q[0]), "=l"(q[1]), "=l"(q[2]), "=l"(q[3]) : "l"(p));
}

// ---------------------------------------------------------------------------
// ALL 50 Sinkhorn iterations. 148 persistent blocks x 1024 threads (1/SM).
// 384 rows/block in SMEM (192KB); 8704 leftover rows from L2 (1 batch/warp).
// Static 6-batch unrolled loop; single-round 32KB Ts staging (1 sync).
// ---------------------------------------------------------------------------
__global__ void __launch_bounds__(1024, 1) k_sink() {
    extern __shared__ char sm[];
    float* Ts  = (float*)(sm + TS_OFF);    // 32 warps x 256 f32 (32KB)
    float* wsh = (float*)(sm + WSH_OFF);   // 256 f32 w broadcast

    const float nuP = 1.f / (float)KK + 1e-8f;
    const float muP = 1.f / (float)BB + 1e-8f;
    int t = threadIdx.x, lane = t & 31, warp = t >> 5;
    int half = lane >> 4, hl = lane & 15;
    int rowBase = blockIdx.x * SROWS;

    // one-time fill: this block's K slab, global -> smem (coalesced uint4)
    {
        const uint4* src = (const uint4*)(g_Kh + (size_t)rowBase * KK);
        uint4* dst = (uint4*)sm;
#pragma unroll 4
        for (int i = t; i < SROWS * 32; i += 1024) dst[i] = src[i];
    }
    __syncthreads();

    for (int it = 1; it <= NITER; it++) {
        int prev = (it - 1) % 3, cur = it % 3, clr = (it + 1) % 3;
        bool last = (it == NITER);

        if (t < 256) wsh[t] = nuP * __fdividef(1.f, __ldcg(&g_T[prev][t * 32]));
        __syncthreads();

        u64 w2[8];
        const float2* wp = (const float2*)&wsh[hl * 16];
#pragma unroll
        for (int m = 0; m < 8; m++) w2[m] = packff(wp[m].x, wp[m].y);

        u64 tj2[8];
#pragma unroll
        for (int m = 0; m < 8; m++) tj2[m] = 0ull;

        // 6 smem batches, contiguous per warp, compile-time trip count
#pragma unroll
        for (int rep = 0; rep < WBATCH; rep++) {
            int lb = warp * WBATCH + rep;
            const ulonglong2* p =
                (const ulonglong2*)(sm + (lb * 2 + half) * 512 + hl * 32);
            ulonglong2 qa = p[0], qb = p[1];
            u64 q[4] = {qa.x, qa.y, qb.x, qb.y};
            comp_row(rowBase + lb * 2 + half, q, w2, tj2, muP, last, hl);
        }
        // leftover global batch (one per warp, warps 0..29)
        if (warp < 30) {
            int gidx = blockIdx.x + SNBLK * warp;
            if (gidx < GBATCH) {
                int row = GSTART + gidx * 2 + half;
                u64 q[4];
                ldq_g(row, hl, q);
                comp_row(row, q, w2, tj2, muP, last, hl);
            }
        }

        // combine the two 16-lane halves (same columns)
#pragma unroll
        for (int m = 0; m < 8; m++) {
            u64 o = __shfl_xor_sync(0xffffffffu, tj2[m], 16);
            tj2[m] = add2(tj2[m], o);
        }
        // single-round staging: every warp owns one Ts row
        if (half == 0) {
            u64* dstT = (u64*)&Ts[warp * 256 + hl * 16];
#pragma unroll
            for (int m = 0; m < 8; m++) dstT[m] = tj2[m];
        }
        __syncthreads();

        // 1024 threads: each sums 8 of the 32 Ts rows for its column,
        // then one spread atomic (4 per g_T address)
        {
            int col = t & 255, grp = t >> 8;
            float s = 0.f;
#pragma unroll
            for (int r = 0; r < 8; r++) s += Ts[(grp * 8 + r) * 256 + col];
            atomicAdd(&g_T[cur][col * 32], s);
        }
        if (blockIdx.x == 0 && t < 256) g_T[clr][t * 32] = 0.f;
        __syncthreads();

        // grid barrier: release-arrive, acquire-spin (monotonic counter)
        if (t == 0) {
            asm volatile("red.release.gpu.global.add.u32 [%0], 1;"
                         :: "l"(&g_bar) : "memory");
            unsigned target = (unsigned)it * SNBLK;
            unsigned v;
            while (true) {
                asm volatile("ld.global.acquire.gpu.u32 %0, [%1];"
                             : "=r"(v) : "l"(&g_bar));
                if (v >= target) break;
                __nanosleep(16);
            }
        }
        __syncthreads();
    }
}

// ---------------------------------------------------------------------------
// final: sum_ij a_i * K'_ij * w_j * C_ij * softmax(|coord_i|)_j
// C reconstructed: C = -0.1 * log(K' - 1e-8).
// ---------------------------------------------------------------------------
__global__ void __launch_bounds__(256, 2) k_final(const float* __restrict__ coord, int cur) {
    const float nuP = 1.f / (float)KK + 1e-8f;
    int t = threadIdx.x, lane = t & 31, warp = t >> 5;

    float w[8];
#pragma unroll
    for (int m = 0; m < 8; m++)
        w[m] = nuP * __fdividef(1.f, g_T[cur][(lane * 8 + m) * 32]);

    float accf = 0.f;
    const int nWarps = 296 * 8;
    const int nBatch = BB / 2;
    int gw = blockIdx.x * 8 + warp;
    int colOff = lane * 8;

    for (int b = gw; b < nBatch; b += nWarps) {
        int row0 = b * 2;
#pragma unroll
        for (int r = 0; r < 2; r++) {
            int row = row0 + r;
            float q[8];
            {
                const float4* Cd = (const float4*)(coord + (size_t)row * KK + colOff);
                float4 c0 = Cd[0], c1 = Cd[1];
                q[0] = fabsf(c0.x); q[1] = fabsf(c0.y); q[2] = fabsf(c0.z); q[3] = fabsf(c0.w);
                q[4] = fabsf(c1.x); q[5] = fabsf(c1.y); q[6] = fabsf(c1.z); q[7] = fabsf(c1.w);
            }
            float mx = q[0];
#pragma unroll
            for (int m = 1; m < 8; m++) mx = fmaxf(mx, q[m]);
#pragma unroll
            for (int o = 16; o; o >>= 1) mx = fmaxf(mx, __shfl_xor_sync(0xffffffffu, mx, o));
            float e[8], z = 0.f;
#pragma unroll
            for (int m = 0; m < 8; m++) { e[m] = __expf(q[m] - mx); z += e[m]; }
#pragma unroll
            for (int o = 16; o; o >>= 1) z += __shfl_xor_sync(0xffffffffu, z, o);
            float rz = __fdividef(1.f, z);

            float a = g_a[row];
            float kk[8];
            {
                uint4 kv = *(const uint4*)&g_Kh[(size_t)row * KK + colOff];
                unsigned u[4] = {kv.x, kv.y, kv.z, kv.w};
#pragma unroll
                for (int i = 0; i < 4; i++) {
                    float2 f2 = __bfloat1622float2(*(__nv_bfloat162*)&u[i]);
                    kk[i * 2] = f2.x; kk[i * 2 + 1] = f2.y;
                }
            }

            float contrib = 0.f;
#pragma unroll
            for (int m = 0; m < 8; m++) {
                float cm = -0.1f * __logf(fmaxf(kk[m] - 1e-8f, 1e-12f));
                contrib += kk[m] * w[m] * cm * e[m];
            }
            accf += a * rz * contrib;
        }
    }

#pragma unroll
    for (int o = 16; o; o >>= 1) accf += __shfl_xor_sync(0xffffffffu, accf, o);
    __shared__ double sw[8];
    if (lane == 0) sw[warp] = (double)accf;
    __syncthreads();
    if (t == 0) {
        double s = 0.0;
#pragma unroll
        for (int i = 0; i < 8; i++) s += sw[i];
        atomicAdd(&g_sum, s);
    }
}

__global__ void k_write(float* out) { out[0] = (float)g_sum; }

// ---------------------------------------------------------------------------
extern "C" void kernel_launch(void* const* d_in, const int* in_sizes, int n_in,
                              void* d_out, int out_size) {
    const float* x     = (const float*)d_in[0];   // (65536, 128)
    const float* proto = (const float*)d_in[1];   // (256, 128)
    const float* coord = (const float*)d_in[2];   // (65536, 256)

    cudaFuncSetAttribute(k_sink, cudaFuncAttributeMaxDynamicSharedMemorySize,
                         SMEM_SINK);

    k_init<<<1, 256>>>(proto);
    k_xnorm<<<BB / 8, 256>>>(x);
    k_gemm<<<BB / 64, 256>>>(x);

    k_sink<<<SNBLK, 1024, SMEM_SINK>>>();

    k_final<<<296, 256>>>(coord, NITER % 3);
    k_write<<<1, 1>>>((float*)d_out);
}

// round 16
// speedup vs baseline: 1.0492x; 1.0492x over previous
#include <cuda_runtime.h>
#include <cuda_bf16.h>
#include <math.h>

#define BB 65536
#define KK 256
#define DD 128
#define NITER 50
#define SNBLK 148          // k_sink: one persistent block per SM
#define SROWS 416          // smem-resident rows per block (208KB slab)
#define SBATCH 208         // 2-row smem batches per block
#define GSTART (SNBLK * SROWS)          // 61568: first global-resident row
#define GBATCH ((BB - GSTART) / 2)      // 1984 leftover 2-row batches
#define TS_OFF (SROWS * 512)            // 212992
#define WSH_OFF (TS_OFF + 16384)        // 229376 (Ts: 16 warps x 256 f32)
#define SMEM_SINK (WSH_OFF + 1024)      // 230400 B

typedef unsigned long long u64;

// ---- scratch (static device globals; no allocation) ----
__device__ __nv_bfloat16 g_Kh[(size_t)BB * KK];  // K' in bf16 (32MB)
__device__ float g_ynT[DD * KK];         // normalized prototypes, k-major [k][j]
__device__ float g_xinv[BB];             // 1 / ||x_i||
__device__ float g_a[BB];                // exp(u)   (written on last iteration)
__device__ float g_T[3][KK * 32];        // column sums, padded 128B apart
__device__ unsigned g_bar;               // grid barrier counter
__device__ double g_sum;

// ---- packed f32x2 helpers ----
__device__ __forceinline__ void fma2(u64& d, u64 a, u64 b) {
    asm("fma.rn.f32x2 %0, %1, %2, %0;" : "+l"(d) : "l"(a), "l"(b));
}
__device__ __forceinline__ u64 add2(u64 a, u64 b) {
    u64 r; asm("add.rn.f32x2 %0, %1, %2;" : "=l"(r) : "l"(a), "l"(b)); return r;
}
__device__ __forceinline__ u64 packff(float lo, float hi) {
    u64 r; asm("mov.b64 %0, {%1, %2};" : "=l"(r) : "f"(lo), "f"(hi)); return r;
}
__device__ __forceinline__ void unpackff(u64 v, float& lo, float& hi) {
    asm("mov.b64 {%0, %1}, %2;" : "=f"(lo), "=f"(hi) : "l"(v));
}
__device__ __forceinline__ u64 bf2_to_f32x2(unsigned v) {
    unsigned lo = v << 16;
    unsigned hi = v & 0xFFFF0000u;
    u64 r; asm("mov.b64 %0, {%1, %2};" : "=l"(r) : "r"(lo), "r"(hi)); return r;
}

// ---------------------------------------------------------------------------
__global__ void k_init(const float* __restrict__ proto) {
    int j = threadIdx.x;  // 0..255
    float ss = 0.f;
#pragma unroll 8
    for (int k = 0; k < DD; k++) { float v = proto[j * DD + k]; ss += v * v; }
    float inv = __fdividef(1.f, fmaxf(sqrtf(ss), 1e-12f));
    for (int k = 0; k < DD; k++) g_ynT[k * KK + j] = proto[j * DD + k] * inv;
    const float nuP = 1.f / (float)KK + 1e-8f;
    g_T[0][j * 32] = nuP;   // makes w == 1 on iteration 1 (v0 = 0)
    g_T[1][j * 32] = 0.f;   // accumulation target of iteration 1
    if (j == 0) { g_sum = 0.0; g_bar = 0u; }
}

// ---------------------------------------------------------------------------
__global__ void k_xnorm(const float* __restrict__ x) {
    int warp = threadIdx.x >> 5, lane = threadIdx.x & 31;
    int row = blockIdx.x * 8 + warp;
    float4 v = ((const float4*)(x + (size_t)row * DD))[lane];
    float ss = v.x * v.x + v.y * v.y + v.z * v.z + v.w * v.w;
#pragma unroll
    for (int o = 16; o; o >>= 1) ss += __shfl_xor_sync(0xffffffffu, ss, o);
    if (lane == 0) g_xinv[row] = __fdividef(1.f, fmaxf(sqrtf(ss), 1e-12f));
}

// ---------------------------------------------------------------------------
// cost GEMM (R10 — proven, untouched): FFMA2; K' = exp(-10*(1-xn.yn))+1e-8, bf16
// ---------------------------------------------------------------------------
__global__ void k_gemm(const float* __restrict__ x) {
    __shared__ float ys[32 * 256];
    __shared__ float xs[64 * 32];
    __shared__ float xrn[64];

    int t = threadIdx.x;
    int rowBase = blockIdx.x * 64;
    if (t < 64) xrn[t] = g_xinv[rowBase + t];

    int tx = t & 31, ty = t >> 5;
    u64 acc[8][4];
#pragma unroll
    for (int i = 0; i < 8; i++)
#pragma unroll
        for (int j = 0; j < 4; j++) acc[i][j] = 0ull;

    for (int kc = 0; kc < 4; kc++) {
        __syncthreads();
        {
            const float4* src = (const float4*)(g_ynT + kc * 32 * 256);
            float4* dst = (float4*)ys;
#pragma unroll
            for (int i = 0; i < 8; i++) dst[t + i * 256] = src[t + i * 256];
        }
        {
#pragma unroll
            for (int i = 0; i < 2; i++) {
                int idx = t + i * 256;
                int r = idx >> 3;
                int c4 = idx & 7;
                float4 v = *(const float4*)(x + (size_t)(rowBase + r) * DD + kc * 32 + c4 * 4);
                *(float4*)&xs[r * 32 + c4 * 4] = v;
            }
        }
        __syncthreads();
#pragma unroll 4
        for (int k = 0; k < 32; k++) {
            float4 b0 = *(const float4*)&ys[k * 256 + tx * 8];
            float4 b1 = *(const float4*)&ys[k * 256 + tx * 8 + 4];
            u64 p0 = packff(b0.x, b0.y), p1 = packff(b0.z, b0.w);
            u64 p2 = packff(b1.x, b1.y), p3 = packff(b1.z, b1.w);
#pragma unroll
            for (int i = 0; i < 8; i++) {
                float a = xs[(ty * 8 + i) * 32 + k];
                u64 a2 = packff(a, a);
                fma2(acc[i][0], a2, p0);
                fma2(acc[i][1], a2, p1);
                fma2(acc[i][2], a2, p2);
                fma2(acc[i][3], a2, p3);
            }
        }
    }

#pragma unroll
    for (int i = 0; i < 8; i++) {
        int row = rowBase + ty * 8 + i;
        float inv = xrn[ty * 8 + i];
        float kv[8];
#pragma unroll
        for (int j = 0; j < 4; j++) {
            float lo, hi; unpackff(acc[i][j], lo, hi);
            float c0 = 1.f - lo * inv;
            float c1 = 1.f - hi * inv;
            kv[2 * j]     = __expf(-10.f * c0) + 1e-8f;
            kv[2 * j + 1] = __expf(-10.f * c1) + 1e-8f;
        }
        __nv_bfloat162 h0 = __float22bfloat162_rn(make_float2(kv[0], kv[1]));
        __nv_bfloat162 h1 = __float22bfloat162_rn(make_float2(kv[2], kv[3]));
        __nv_bfloat162 h2 = __float22bfloat162_rn(make_float2(kv[4], kv[5]));
        __nv_bfloat162 h3 = __float22bfloat162_rn(make_float2(kv[6], kv[7]));
        uint4 s;
        s.x = *(unsigned*)&h0; s.y = *(unsigned*)&h1;
        s.z = *(unsigned*)&h2; s.w = *(unsigned*)&h3;
        *(uint4*)&g_Kh[(size_t)row * KK + tx * 8] = s;
    }
}

// ---------------------------------------------------------------------------
// one row-half (16 bf16 in q[4]): s over 16-lane half, a = mu/s, tj += K*a
// ---------------------------------------------------------------------------
__device__ __forceinline__ void comp_row(int row, const u64* q, const u64* w2,
                                         u64* tj2, float muP, bool storeA, int hl) {
    u64 pr[8];
#pragma unroll
    for (int i = 0; i < 4; i++) {
        unsigned lo32 = (unsigned)(q[i] & 0xffffffffull);
        unsigned hi32 = (unsigned)(q[i] >> 32);
        pr[2 * i]     = bf2_to_f32x2(lo32);
        pr[2 * i + 1] = bf2_to_f32x2(hi32);
    }
    u64 t0 = 0, t1 = 0, t2 = 0, t3 = 0;
    fma2(t0, pr[0], w2[0]); fma2(t1, pr[1], w2[1]);
    fma2(t2, pr[2], w2[2]); fma2(t3, pr[3], w2[3]);
    fma2(t0, pr[4], w2[4]); fma2(t1, pr[5], w2[5]);
    fma2(t2, pr[6], w2[6]); fma2(t3, pr[7], w2[7]);
    u64 tt = add2(add2(t0, t1), add2(t2, t3));
    float slo, shi; unpackff(tt, slo, shi);
    float s = slo + shi;
#pragma unroll
    for (int o = 8; o; o >>= 1) s += __shfl_xor_sync(0xffffffffu, s, o);
    float a = muP * __fdividef(1.f, s);
    if (storeA && hl == 0) g_a[row] = a;
    u64 a2 = packff(a, a);
#pragma unroll
    for (int k = 0; k < 8; k++) fma2(tj2[k], pr[k], a2);
}

__device__ __forceinline__ void ldq_g(int row, int hl, u64* q) {
    const __nv_bfloat16* p = g_Kh + (size_t)row * KK + hl * 16;
    asm volatile("ld.global.L2::evict_last.v4.b64 {%0,%1,%2,%3}, [%4];"
                 : "=l"(q[0]), "=l"(q[1]), "=l"(q[2]), "=l"(q[3]) : "l"(p));
}

// ---------------------------------------------------------------------------
// ALL 50 Sinkhorn iterations. 148 persistent blocks x 1024 threads (1/SM).
// 416 rows/block in SMEM (208KB); 3968 leftover rows from L2, one batch for
// warps 16-29, PREFETCHED before the smem loop (latency hidden).
// Dynamic smem batch loop (R14 structure — no unroll, no spills);
// 2-round Ts staging (4 syncs/iter vs R14's 8).
// ---------------------------------------------------------------------------
__global__ void __launch_bounds__(1024, 1) k_sink() {
    extern __shared__ char sm[];
    float* Ts  = (float*)(sm + TS_OFF);    // 16 warps x 256 f32 (16KB)
    float* wsh = (float*)(sm + WSH_OFF);   // 256 f32 w broadcast

    const float nuP = 1.f / (float)KK + 1e-8f;
    const float muP = 1.f / (float)BB + 1e-8f;
    int t = threadIdx.x, lane = t & 31, warp = t >> 5;
    int half = lane >> 4, hl = lane & 15;
    int rowBase = blockIdx.x * SROWS;

    // leftover-batch assignment (warps 16..29, one 2-row batch each)
    int grow = -1;
    if (warp >= 16 && warp < 30) {
        int gidx = blockIdx.x + SNBLK * (warp - 16);
        if (gidx < GBATCH) grow = GSTART + gidx * 2 + half;
    }

    // one-time fill: this block's K slab, global -> smem (coalesced uint4)
    {
        const uint4* src = (const uint4*)(g_Kh + (size_t)rowBase * KK);
        uint4* dst = (uint4*)sm;
#pragma unroll 4
        for (int i = t; i < SROWS * 32; i += 1024) dst[i] = src[i];
    }
    __syncthreads();

    for (int it = 1; it <= NITER; it++) {
        int prev = (it - 1) % 3, cur = it % 3, clr = (it + 1) % 3;
        bool last = (it == NITER);

        if (t < 256) wsh[t] = nuP * __fdividef(1.f, __ldcg(&g_T[prev][t * 32]));
        __syncthreads();

        u64 w2[8];
        const float2* wp = (const float2*)&wsh[hl * 16];
#pragma unroll
        for (int m = 0; m < 8; m++) w2[m] = packff(wp[m].x, wp[m].y);

        u64 tj2[8];
#pragma unroll
        for (int m = 0; m < 8; m++) tj2[m] = 0ull;

        // prefetch the leftover global batch NOW (compute after smem loop)
        u64 qg[4];
        if (grow >= 0) ldq_g(grow, hl, qg);

        // smem batches: dynamic loop (R14 structure)
        for (int lb = warp; lb < SBATCH; lb += 32) {
            const ulonglong2* p =
                (const ulonglong2*)(sm + (lb * 2 + half) * 512 + hl * 32);
            ulonglong2 qa = p[0], qb = p[1];
            u64 q[4] = {qa.x, qa.y, qb.x, qb.y};
            comp_row(rowBase + lb * 2 + half, q, w2, tj2, muP, last, hl);
        }
        // leftover global batch (data already in flight / arrived)
        if (grow >= 0) comp_row(grow, qg, w2, tj2, muP, last, hl);

        // combine the two 16-lane halves (same columns)
#pragma unroll
        for (int m = 0; m < 8; m++) {
            u64 o = __shfl_xor_sync(0xffffffffu, tj2[m], 16);
            tj2[m] = add2(tj2[m], o);
        }

        // 2-round staged reduction: 16 warps write per round, 256 threads sum
        float accT = 0.f;
#pragma unroll 1
        for (int r = 0; r < 2; r++) {
            if ((warp >> 4) == r && half == 0) {
                u64* dstT = (u64*)&Ts[(warp & 15) * 256 + hl * 16];
#pragma unroll
                for (int m = 0; m < 8; m++) dstT[m] = tj2[m];
            }
            __syncthreads();
            if (t < 256) {
#pragma unroll
                for (int rr = 0; rr < 16; rr++) accT += Ts[rr * 256 + t];
            }
            __syncthreads();
        }

        if (blockIdx.x == 0 && t < 256) g_T[clr][t * 32] = 0.f;
        if (t < 256) atomicAdd(&g_T[cur][t * 32], accT);
        __syncthreads();

        // grid barrier: release-arrive, acquire-spin (monotonic counter)
        if (t == 0) {
            asm volatile("red.release.gpu.global.add.u32 [%0], 1;"
                         :: "l"(&g_bar) : "memory");
            unsigned target = (unsigned)it * SNBLK;
            unsigned v;
            while (true) {
                asm volatile("ld.global.acquire.gpu.u32 %0, [%1];"
                             : "=r"(v) : "l"(&g_bar));
                if (v >= target) break;
                __nanosleep(16);
            }
        }
        __syncthreads();
    }
}

// ---------------------------------------------------------------------------
// final: sum_ij a_i * K'_ij * w_j * C_ij * softmax(|coord_i|)_j
// C reconstructed: C = -0.1 * log(K' - 1e-8).
// ---------------------------------------------------------------------------
__global__ void __launch_bounds__(256, 2) k_final(const float* __restrict__ coord, int cur) {
    const float nuP = 1.f / (float)KK + 1e-8f;
    int t = threadIdx.x, lane = t & 31, warp = t >> 5;

    float w[8];
#pragma unroll
    for (int m = 0; m < 8; m++)
        w[m] = nuP * __fdividef(1.f, g_T[cur][(lane * 8 + m) * 32]);

    float accf = 0.f;
    const int nWarps = 296 * 8;
    const int nBatch = BB / 2;
    int gw = blockIdx.x * 8 + warp;
    int colOff = lane * 8;

    for (int b = gw; b < nBatch; b += nWarps) {
        int row0 = b * 2;
#pragma unroll
        for (int r = 0; r < 2; r++) {
            int row = row0 + r;
            float q[8];
            {
                const float4* Cd = (const float4*)(coord + (size_t)row * KK + colOff);
                float4 c0 = Cd[0], c1 = Cd[1];
                q[0] = fabsf(c0.x); q[1] = fabsf(c0.y); q[2] = fabsf(c0.z); q[3] = fabsf(c0.w);
                q[4] = fabsf(c1.x); q[5] = fabsf(c1.y); q[6] = fabsf(c1.z); q[7] = fabsf(c1.w);
            }
            float mx = q[0];
#pragma unroll
            for (int m = 1; m < 8; m++) mx = fmaxf(mx, q[m]);
#pragma unroll
            for (int o = 16; o; o >>= 1) mx = fmaxf(mx, __shfl_xor_sync(0xffffffffu, mx, o));
            float e[8], z = 0.f;
#pragma unroll
            for (int m = 0; m < 8; m++) { e[m] = __expf(q[m] - mx); z += e[m]; }
#pragma unroll
            for (int o = 16; o; o >>= 1) z += __shfl_xor_sync(0xffffffffu, z, o);
            float rz = __fdividef(1.f, z);

            float a = g_a[row];
            float kk[8];
            {
                uint4 kv = *(const uint4*)&g_Kh[(size_t)row * KK + colOff];
                unsigned u[4] = {kv.x, kv.y, kv.z, kv.w};
#pragma unroll
                for (int i = 0; i < 4; i++) {
                    float2 f2 = __bfloat1622float2(*(__nv_bfloat162*)&u[i]);
                    kk[i * 2] = f2.x; kk[i * 2 + 1] = f2.y;
                }
            }

            float contrib = 0.f;
#pragma unroll
            for (int m = 0; m < 8; m++) {
                float cm = -0.1f * __logf(fmaxf(kk[m] - 1e-8f, 1e-12f));
                contrib += kk[m] * w[m] * cm * e[m];
            }
            accf += a * rz * contrib;
        }
    }

#pragma unroll
    for (int o = 16; o; o >>= 1) accf += __shfl_xor_sync(0xffffffffu, accf, o);
    __shared__ double sw[8];
    if (lane == 0) sw[warp] = (double)accf;
    __syncthreads();
    if (t == 0) {
        double s = 0.0;
#pragma unroll
        for (int i = 0; i < 8; i++) s += sw[i];
        atomicAdd(&g_sum, s);
    }
}

__global__ void k_write(float* out) { out[0] = (float)g_sum; }

// ---------------------------------------------------------------------------
extern "C" void kernel_launch(void* const* d_in, const int* in_sizes, int n_in,
                              void* d_out, int out_size) {
    const float* x     = (const float*)d_in[0];   // (65536, 128)
    const float* proto = (const float*)d_in[1];   // (256, 128)
    const float* coord = (const float*)d_in[2];   // (65536, 256)

    cudaFuncSetAttribute(k_sink, cudaFuncAttributeMaxDynamicSharedMemorySize,
                         SMEM_SINK);

    k_init<<<1, 256>>>(proto);
    k_xnorm<<<BB / 8, 256>>>(x);
    k_gemm<<<BB / 64, 256>>>(x);

    k_sink<<<SNBLK, 1024, SMEM_SINK>>>();

    k_final<<<296, 256>>>(coord, NITER % 3);
    k_write<<<1, 1>>>((float*)d_out);
}

// round 17
// speedup vs baseline: 1.1662x; 1.1115x over previous
#include <cuda_runtime.h>
#include <cuda_bf16.h>
#include <math.h>

#define BB 65536
#define KK 256
#define DD 128
#define NITER 50
#define SNBLK 148          // k_sink: one persistent block per SM
#define SROWS 416          // smem-resident rows per block (208KB slab)
#define SBATCH 208         // 2-row smem batches per block
#define GSTART (SNBLK * SROWS)          // 61568: first global-resident row
#define GBATCH ((BB - GSTART) / 2)      // 1984 leftover 2-row batches
#define TS_OFF (SROWS * 512)            // 212992
#define WSH_OFF (TS_OFF + 16384)        // 229376 (Ts: 16 warps x 256 f32)
#define SMEM_SINK (WSH_OFF + 1024)      // 230400 B

typedef unsigned long long u64;

// ---- scratch (static device globals; no allocation) ----
__device__ __nv_bfloat16 g_Kh[(size_t)BB * KK];  // K' in bf16 (32MB)
__device__ float g_ynT[DD * KK];         // normalized prototypes, k-major [k][j]
__device__ float g_xinv[BB];             // 1 / ||x_i||
__device__ float g_a[BB];                // exp(u)   (written on last iteration)
__device__ float g_T[3][KK * 32];        // column sums, padded 128B apart
__device__ unsigned g_bar;               // grid barrier counter
__device__ double g_sum;

// ---- packed f32x2 helpers ----
__device__ __forceinline__ void fma2(u64& d, u64 a, u64 b) {
    asm("fma.rn.f32x2 %0, %1, %2, %0;" : "+l"(d) : "l"(a), "l"(b));
}
__device__ __forceinline__ u64 add2(u64 a, u64 b) {
    u64 r; asm("add.rn.f32x2 %0, %1, %2;" : "=l"(r) : "l"(a), "l"(b)); return r;
}
__device__ __forceinline__ u64 packff(float lo, float hi) {
    u64 r; asm("mov.b64 %0, {%1, %2};" : "=l"(r) : "f"(lo), "f"(hi)); return r;
}
__device__ __forceinline__ void unpackff(u64 v, float& lo, float& hi) {
    asm("mov.b64 {%0, %1}, %2;" : "=f"(lo), "=f"(hi) : "l"(v));
}
__device__ __forceinline__ u64 bf2_to_f32x2(unsigned v) {
    unsigned lo = v << 16;
    unsigned hi = v & 0xFFFF0000u;
    u64 r; asm("mov.b64 %0, {%1, %2};" : "=l"(r) : "r"(lo), "r"(hi)); return r;
}

// ---------------------------------------------------------------------------
__global__ void k_init(const float* __restrict__ proto) {
    int j = threadIdx.x;  // 0..255
    float ss = 0.f;
#pragma unroll 8
    for (int k = 0; k < DD; k++) { float v = proto[j * DD + k]; ss += v * v; }
    float inv = __fdividef(1.f, fmaxf(sqrtf(ss), 1e-12f));
    for (int k = 0; k < DD; k++) g_ynT[k * KK + j] = proto[j * DD + k] * inv;
    const float nuP = 1.f / (float)KK + 1e-8f;
    g_T[0][j * 32] = nuP;   // makes w == 1 on iteration 1 (v0 = 0)
    g_T[1][j * 32] = 0.f;   // accumulation target of iteration 1
    if (j == 0) { g_sum = 0.0; g_bar = 0u; }
}

// ---------------------------------------------------------------------------
__global__ void k_xnorm(const float* __restrict__ x) {
    int warp = threadIdx.x >> 5, lane = threadIdx.x & 31;
    int row = blockIdx.x * 8 + warp;
    float4 v = ((const float4*)(x + (size_t)row * DD))[lane];
    float ss = v.x * v.x + v.y * v.y + v.z * v.z + v.w * v.w;
#pragma unroll
    for (int o = 16; o; o >>= 1) ss += __shfl_xor_sync(0xffffffffu, ss, o);
    if (lane == 0) g_xinv[row] = __fdividef(1.f, fmaxf(sqrtf(ss), 1e-12f));
}

// ---------------------------------------------------------------------------
// cost GEMM (R10 — proven, untouched): FFMA2; K' = exp(-10*(1-xn.yn))+1e-8, bf16
// ---------------------------------------------------------------------------
__global__ void k_gemm(const float* __restrict__ x) {
    __shared__ float ys[32 * 256];
    __shared__ float xs[64 * 32];
    __shared__ float xrn[64];

    int t = threadIdx.x;
    int rowBase = blockIdx.x * 64;
    if (t < 64) xrn[t] = g_xinv[rowBase + t];

    int tx = t & 31, ty = t >> 5;
    u64 acc[8][4];
#pragma unroll
    for (int i = 0; i < 8; i++)
#pragma unroll
        for (int j = 0; j < 4; j++) acc[i][j] = 0ull;

    for (int kc = 0; kc < 4; kc++) {
        __syncthreads();
        {
            const float4* src = (const float4*)(g_ynT + kc * 32 * 256);
            float4* dst = (float4*)ys;
#pragma unroll
            for (int i = 0; i < 8; i++) dst[t + i * 256] = src[t + i * 256];
        }
        {
#pragma unroll
            for (int i = 0; i < 2; i++) {
                int idx = t + i * 256;
                int r = idx >> 3;
                int c4 = idx & 7;
                float4 v = *(const float4*)(x + (size_t)(rowBase + r) * DD + kc * 32 + c4 * 4);
                *(float4*)&xs[r * 32 + c4 * 4] = v;
            }
        }
        __syncthreads();
#pragma unroll 4
        for (int k = 0; k < 32; k++) {
            float4 b0 = *(const float4*)&ys[k * 256 + tx * 8];
            float4 b1 = *(const float4*)&ys[k * 256 + tx * 8 + 4];
            u64 p0 = packff(b0.x, b0.y), p1 = packff(b0.z, b0.w);
            u64 p2 = packff(b1.x, b1.y), p3 = packff(b1.z, b1.w);
#pragma unroll
            for (int i = 0; i < 8; i++) {
                float a = xs[(ty * 8 + i) * 32 + k];
                u64 a2 = packff(a, a);
                fma2(acc[i][0], a2, p0);
                fma2(acc[i][1], a2, p1);
                fma2(acc[i][2], a2, p2);
                fma2(acc[i][3], a2, p3);
            }
        }
    }

#pragma unroll
    for (int i = 0; i < 8; i++) {
        int row = rowBase + ty * 8 + i;
        float inv = xrn[ty * 8 + i];
        float kv[8];
#pragma unroll
        for (int j = 0; j < 4; j++) {
            float lo, hi; unpackff(acc[i][j], lo, hi);
            float c0 = 1.f - lo * inv;
            float c1 = 1.f - hi * inv;
            kv[2 * j]     = __expf(-10.f * c0) + 1e-8f;
            kv[2 * j + 1] = __expf(-10.f * c1) + 1e-8f;
        }
        __nv_bfloat162 h0 = __float22bfloat162_rn(make_float2(kv[0], kv[1]));
        __nv_bfloat162 h1 = __float22bfloat162_rn(make_float2(kv[2], kv[3]));
        __nv_bfloat162 h2 = __float22bfloat162_rn(make_float2(kv[4], kv[5]));
        __nv_bfloat162 h3 = __float22bfloat162_rn(make_float2(kv[6], kv[7]));
        uint4 s;
        s.x = *(unsigned*)&h0; s.y = *(unsigned*)&h1;
        s.z = *(unsigned*)&h2; s.w = *(unsigned*)&h3;
        *(uint4*)&g_Kh[(size_t)row * KK + tx * 8] = s;
    }
}

// ---------------------------------------------------------------------------
// one row-half: lane hl owns cols [hl*8, hl*8+8) and [128+hl*8, 128+hl*8+8)
// (two 16B chunks -> conflict-free 16B-stride smem access).
// q[0],q[1] = first chunk; q[2],q[3] = second chunk.
// ---------------------------------------------------------------------------
__device__ __forceinline__ void comp_row(int row, const u64* q, const u64* w2,
                                         u64* tj2, float muP, bool storeA, int hl) {
    u64 pr[8];
#pragma unroll
    for (int i = 0; i < 4; i++) {
        unsigned lo32 = (unsigned)(q[i] & 0xffffffffull);
        unsigned hi32 = (unsigned)(q[i] >> 32);
        pr[2 * i]     = bf2_to_f32x2(lo32);
        pr[2 * i + 1] = bf2_to_f32x2(hi32);
    }
    u64 t0 = 0, t1 = 0, t2 = 0, t3 = 0;
    fma2(t0, pr[0], w2[0]); fma2(t1, pr[1], w2[1]);
    fma2(t2, pr[2], w2[2]); fma2(t3, pr[3], w2[3]);
    fma2(t0, pr[4], w2[4]); fma2(t1, pr[5], w2[5]);
    fma2(t2, pr[6], w2[6]); fma2(t3, pr[7], w2[7]);
    u64 tt = add2(add2(t0, t1), add2(t2, t3));
    float slo, shi; unpackff(tt, slo, shi);
    float s = slo + shi;
#pragma unroll
    for (int o = 8; o; o >>= 1) s += __shfl_xor_sync(0xffffffffu, s, o);
    float a = muP * __fdividef(1.f, s);
    if (storeA && hl == 0) g_a[row] = a;
    u64 a2 = packff(a, a);
#pragma unroll
    for (int k = 0; k < 8; k++) fma2(tj2[k], pr[k], a2);
}

// leftover global batch: same split-chunk column mapping (2x LDG.128)
__device__ __forceinline__ void ldq_g(int row, int hl, u64* q) {
    const u64* pA = (const u64*)(g_Kh + (size_t)row * KK + hl * 8);
    const u64* pB = (const u64*)(g_Kh + (size_t)row * KK + 128 + hl * 8);
    q[0] = pA[0]; q[1] = pA[1];
    q[2] = pB[0]; q[3] = pB[1];
}

// ---------------------------------------------------------------------------
// ALL 50 Sinkhorn iterations. 148 persistent blocks x 1024 threads (1/SM).
// 416 rows/block in SMEM; conflict-free 16B-stride lane mapping.
// ---------------------------------------------------------------------------
__global__ void __launch_bounds__(1024, 1) k_sink() {
    extern __shared__ char sm[];
    float* Ts  = (float*)(sm + TS_OFF);    // 16 warps x 256 f32 (16KB)
    float* wsh = (float*)(sm + WSH_OFF);   // 256 f32 w broadcast

    const float nuP = 1.f / (float)KK + 1e-8f;
    const float muP = 1.f / (float)BB + 1e-8f;
    int t = threadIdx.x, lane = t & 31, warp = t >> 5;
    int half = lane >> 4, hl = lane & 15;
    int rowBase = blockIdx.x * SROWS;

    // leftover-batch assignment (warps 16..29, one 2-row batch each)
    int grow = -1;
    if (warp >= 16 && warp < 30) {
        int gidx = blockIdx.x + SNBLK * (warp - 16);
        if (gidx < GBATCH) grow = GSTART + gidx * 2 + half;
    }

    // one-time fill: this block's K slab, global -> smem (coalesced uint4)
    {
        const uint4* src = (const uint4*)(g_Kh + (size_t)rowBase * KK);
        uint4* dst = (uint4*)sm;
#pragma unroll 4
        for (int i = t; i < SROWS * 32; i += 1024) dst[i] = src[i];
    }
    __syncthreads();

    for (int it = 1; it <= NITER; it++) {
        int prev = (it - 1) % 3, cur = it % 3, clr = (it + 1) % 3;
        bool last = (it == NITER);

        if (t < 256) wsh[t] = nuP * __fdividef(1.f, __ldcg(&g_T[prev][t * 32]));
        __syncthreads();

        // split-chunk w mapping: cols hl*8.. and 128+hl*8..
        u64 w2[8];
        {
            const float2* wpA = (const float2*)&wsh[hl * 8];
            const float2* wpB = (const float2*)&wsh[128 + hl * 8];
#pragma unroll
            for (int m = 0; m < 4; m++) {
                w2[m]     = packff(wpA[m].x, wpA[m].y);
                w2[4 + m] = packff(wpB[m].x, wpB[m].y);
            }
        }

        u64 tj2[8];
#pragma unroll
        for (int m = 0; m < 8; m++) tj2[m] = 0ull;

        // prefetch the leftover global batch NOW (compute after smem loop)
        u64 qg[4];
        if (grow >= 0) ldq_g(grow, hl, qg);

        // smem batches: conflict-free 16B-stride loads
        for (int lb = warp; lb < SBATCH; lb += 32) {
            const char* rp = sm + (lb * 2 + half) * 512;
            ulonglong2 qa = *(const ulonglong2*)(rp + hl * 16);
            ulonglong2 qb = *(const ulonglong2*)(rp + 256 + hl * 16);
            u64 q[4] = {qa.x, qa.y, qb.x, qb.y};
            comp_row(rowBase + lb * 2 + half, q, w2, tj2, muP, last, hl);
        }
        // leftover global batch (data already in flight / arrived)
        if (grow >= 0) comp_row(grow, qg, w2, tj2, muP, last, hl);

        // combine the two 16-lane halves (same columns)
#pragma unroll
        for (int m = 0; m < 8; m++) {
            u64 o = __shfl_xor_sync(0xffffffffu, tj2[m], 16);
            tj2[m] = add2(tj2[m], o);
        }

        // 2-round staged reduction (split-chunk store: 16B stride, no conflict)
        float accT = 0.f;
#pragma unroll 1
        for (int r = 0; r < 2; r++) {
            if ((warp >> 4) == r && half == 0) {
                u64* dstA = (u64*)&Ts[(warp & 15) * 256 + hl * 8];
                u64* dstB = (u64*)&Ts[(warp & 15) * 256 + 128 + hl * 8];
#pragma unroll
                for (int m = 0; m < 4; m++) {
                    dstA[m] = tj2[m];
                    dstB[m] = tj2[4 + m];
                }
            }
            __syncthreads();
            if (t < 256) {
#pragma unroll
                for (int rr = 0; rr < 16; rr++) accT += Ts[rr * 256 + t];
            }
            __syncthreads();
        }

        if (blockIdx.x == 0 && t < 256) g_T[clr][t * 32] = 0.f;
        if (t < 256) atomicAdd(&g_T[cur][t * 32], accT);
        __syncthreads();

        // grid barrier: release-arrive, acquire-spin (monotonic counter)
        if (t == 0) {
            asm volatile("red.release.gpu.global.add.u32 [%0], 1;"
                         :: "l"(&g_bar) : "memory");
            unsigned target = (unsigned)it * SNBLK;
            unsigned v;
            while (true) {
                asm volatile("ld.global.acquire.gpu.u32 %0, [%1];"
                             : "=r"(v) : "l"(&g_bar));
                if (v >= target) break;
                __nanosleep(16);
            }
        }
        __syncthreads();
    }
}

// ---------------------------------------------------------------------------
// final: sum_ij a_i * K'_ij * w_j * C_ij * softmax(|coord_i|)_j
// C reconstructed: C = -0.1 * log(K' - 1e-8).
// ---------------------------------------------------------------------------
__global__ void __launch_bounds__(256, 2) k_final(const float* __restrict__ coord, int cur) {
    const float nuP = 1.f / (float)KK + 1e-8f;
    int t = threadIdx.x, lane = t & 31, warp = t >> 5;

    float w[8];
#pragma unroll
    for (int m = 0; m < 8; m++)
        w[m] = nuP * __fdividef(1.f, g_T[cur][(lane * 8 + m) * 32]);

    float accf = 0.f;
    const int nWarps = 296 * 8;
    const int nBatch = BB / 2;
    int gw = blockIdx.x * 8 + warp;
    int colOff = lane * 8;

    for (int b = gw; b < nBatch; b += nWarps) {
        int row0 = b * 2;
#pragma unroll
        for (int r = 0; r < 2; r++) {
            int row = row0 + r;
            float q[8];
            {
                const float4* Cd = (const float4*)(coord + (size_t)row * KK + colOff);
                float4 c0 = Cd[0], c1 = Cd[1];
                q[0] = fabsf(c0.x); q[1] = fabsf(c0.y); q[2] = fabsf(c0.z); q[3] = fabsf(c0.w);
                q[4] = fabsf(c1.x); q[5] = fabsf(c1.y); q[6] = fabsf(c1.z); q[7] = fabsf(c1.w);
            }
            float mx = q[0];
#pragma unroll
            for (int m = 1; m < 8; m++) mx = fmaxf(mx, q[m]);
#pragma unroll
            for (int o = 16; o; o >>= 1) mx = fmaxf(mx, __shfl_xor_sync(0xffffffffu, mx, o));
            float e[8], z = 0.f;
#pragma unroll
            for (int m = 0; m < 8; m++) { e[m] = __expf(q[m] - mx); z += e[m]; }
#pragma unroll
            for (int o = 16; o; o >>= 1) z += __shfl_xor_sync(0xffffffffu, z, o);
            float rz = __fdividef(1.f, z);

            float a = g_a[row];
            float kk[8];
            {
                uint4 kv = *(const uint4*)&g_Kh[(size_t)row * KK + colOff];
                unsigned u[4] = {kv.x, kv.y, kv.z, kv.w};
#pragma unroll
                for (int i = 0; i < 4; i++) {
                    float2 f2 = __bfloat1622float2(*(__nv_bfloat162*)&u[i]);
                    kk[i * 2] = f2.x; kk[i * 2 + 1] = f2.y;
                }
            }

            float contrib = 0.f;
#pragma unroll
            for (int m = 0; m < 8; m++) {
                float cm = -0.1f * __logf(fmaxf(kk[m] - 1e-8f, 1e-12f));
                contrib += kk[m] * w[m] * cm * e[m];
            }
            accf += a * rz * contrib;
        }
    }

#pragma unroll
    for (int o = 16; o; o >>= 1) accf += __shfl_xor_sync(0xffffffffu, accf, o);
    __shared__ double sw[8];
    if (lane == 0) sw[warp] = (double)accf;
    __syncthreads();
    if (t == 0) {
        double s = 0.0;
#pragma unroll
        for (int i = 0; i < 8; i++) s += sw[i];
        atomicAdd(&g_sum, s);
    }
}

__global__ void k_write(float* out) { out[0] = (float)g_sum; }

// ---------------------------------------------------------------------------
extern "C" void kernel_launch(void* const* d_in, const int* in_sizes, int n_in,
                              void* d_out, int out_size) {
    const float* x     = (const float*)d_in[0];   // (65536, 128)
    const float* proto = (const float*)d_in[1];   // (256, 128)
    const float* coord = (const float*)d_in[2];   // (65536, 256)

    cudaFuncSetAttribute(k_sink, cudaFuncAttributeMaxDynamicSharedMemorySize,
                         SMEM_SINK);

    k_init<<<1, 256>>>(proto);
    k_xnorm<<<BB / 8, 256>>>(x);
    k_gemm<<<BB / 64, 256>>>(x);

    k_sink<<<SNBLK, 1024, SMEM_SINK>>>();

    k_final<<<296, 256>>>(coord, NITER % 3);
    k_write<<<1, 1>>>((float*)d_out);
}